// round 1
// baseline (speedup 1.0000x reference)
#include <cuda_runtime.h>

// MxCorrelation: out[b, (p+4)*9+(q+4), y, x] = (1/128) * sum_c a[b,c,y,x] * b[b,c,y+p,x+q]
// p,q in [-4,4], b zero-padded outside [0,128). Shapes: in (8,128,128,128) f32, out (8,81,128,128) f32.
//
// Strategy: FMA-bound tiling.
//  - thread owns 4 aligned x outputs (float4 ops, 3x LDS.128 window per (c,p))
//  - 3 p-rows per block (grid dim), acc[3][9][4] = 108 regs
//  - c processed in chunks of 4 through shared memory
//  - 128 threads/block (32 x-quads * 4 y), 3 blocks/SM target

#define TY   4
#define CC   4
#define BR   (TY + 2)     // 6 b-rows per p-group
#define BW   136          // 128 + 2*4 halo
#define NTHR 128

__global__ __launch_bounds__(NTHR, 3)
void corr_kernel(const float* __restrict__ A, const float* __restrict__ Bm,
                 float* __restrict__ O) {
    __shared__ __align__(16) float sA[CC][TY][128];   // 8 KB
    __shared__ __align__(16) float sB[CC][BR][BW];    // ~12.75 KB

    const int t  = threadIdx.x;
    const int xq = t & 31;          // 0..31
    const int yy = t >> 5;          // 0..3  (whole warp shares yy)
    const int x0 = xq << 2;         // aligned x base

    const int y0 = blockIdx.x * TY;           // 0..124
    const int p0 = (int)blockIdx.y * 3 - 4;   // -4, -1, 2
    const int bb = blockIdx.z;

    const float* Ab = A  + (size_t)bb * 128 * 128 * 128;
    const float* Bb = Bm + (size_t)bb * 128 * 128 * 128;

    float acc[3][9][4];
#pragma unroll
    for (int pp = 0; pp < 3; pp++)
#pragma unroll
        for (int q = 0; q < 9; q++)
#pragma unroll
            for (int j = 0; j < 4; j++) acc[pp][q][j] = 0.0f;

    for (int cc = 0; cc < 128; cc += CC) {
        __syncthreads();

        // ---- fill A tile: CC * TY * 128 = 2048 floats, coalesced rows ----
#pragma unroll
        for (int k = 0; k < (CC * TY * 128) / NTHR; k++) {
            int idx = t + k * NTHR;
            int c   = idx >> 9;          // / 512
            int rem = idx & 511;
            int y   = rem >> 7;
            int x   = rem & 127;
            sA[c][y][x] = Ab[(size_t)(cc + c) * 16384 + (y0 + y) * 128 + x];
        }

        // ---- fill B tile: CC * BR * BW = 3264 floats, zero-padded halo ----
        for (int idx = t; idx < CC * BR * BW; idx += NTHR) {
            int c   = idx / (BR * BW);
            int rem = idx - c * (BR * BW);
            int r   = rem / BW;
            int i   = rem - r * BW;
            int gy  = y0 + p0 + r;       // b row for this p-group
            int gx  = i - 4;             // halo shift
            float v = 0.0f;
            if ((unsigned)gy < 128u && (unsigned)gx < 128u)
                v = Bb[(size_t)(cc + c) * 16384 + gy * 128 + gx];
            sB[c][r][i] = v;
        }
        __syncthreads();

        // ---- compute: per channel, 3 p-rows x 9 q x 4 x = 108 FMAs ----
#pragma unroll
        for (int c = 0; c < CC; c++) {
            float4 av = *(const float4*)&sA[c][yy][x0];
#pragma unroll
            for (int pp = 0; pp < 3; pp++) {
                const float* row = &sB[c][yy + pp][0];
                float w[12];
                *(float4*)&w[0] = *(const float4*)&row[x0];
                *(float4*)&w[4] = *(const float4*)&row[x0 + 4];
                *(float4*)&w[8] = *(const float4*)&row[x0 + 8];
#pragma unroll
                for (int q = 0; q < 9; q++) {
                    acc[pp][q][0] += av.x * w[q];
                    acc[pp][q][1] += av.y * w[q + 1];
                    acc[pp][q][2] += av.z * w[q + 2];
                    acc[pp][q][3] += av.w * w[q + 3];
                }
            }
        }
    }

    // ---- epilogue: scale by 1/128, float4 coalesced stores ----
    const float scale = 1.0f / 128.0f;
    float* Ob = O + (size_t)bb * 81 * 16384;
#pragma unroll
    for (int pp = 0; pp < 3; pp++) {
        int dbase = (p0 + pp + 4) * 9;
#pragma unroll
        for (int q = 0; q < 9; q++) {
            float4 v;
            v.x = acc[pp][q][0] * scale;
            v.y = acc[pp][q][1] * scale;
            v.z = acc[pp][q][2] * scale;
            v.w = acc[pp][q][3] * scale;
            *(float4*)&Ob[(size_t)(dbase + q) * 16384 + (y0 + yy) * 128 + x0] = v;
        }
    }
}

extern "C" void kernel_launch(void* const* d_in, const int* in_sizes, int n_in,
                              void* d_out, int out_size) {
    const float* A = (const float*)d_in[0];   // input1
    const float* B = (const float*)d_in[1];   // input2
    float*       O = (float*)d_out;           // (8, 81, 128, 128)

    dim3 grid(32, 3, 8);  // ytiles, p-groups, batch
    corr_kernel<<<grid, NTHR>>>(A, B, O);
}

// round 2
// speedup vs baseline: 2.8397x; 2.8397x over previous
#include <cuda_runtime.h>

// MxCorrelation: out[b, (p+4)*9+(q+4), y, x] = (1/128) * sum_c a[b,c,y,x] * b[b,c,y+p,x+q]
// p,q in [-4,4], b zero-padded. in (8,128,128,128) f32, out (8,81,128,128) f32.
//
// R2: FFMA-dense mainloop.
//  - A read directly from global (coalesced float4, prefetched) -- no sA
//  - sB double-buffered, filled via cp.async.cg (6 x 16B per thread per chunk)
//  - halo + invalid rows zeroed ONCE (B padding is invariant across channels)
//  - fill descriptors (ptr/saddr/valid) hoisted out of the loop
//  - 1 __syncthreads per chunk, fill(i+1) overlaps compute(i)

#define TY   4
#define CC   4
#define BR   (TY + 2)          // 6 b-rows per p-group
#define BW   144               // 4 halo | 128 interior | 12 pad  (16B-aligned rows)
#define NTHR 128
#define NCH  (128 / CC)        // 32 chunks
#define SBHALF (CC * BR * BW * 4)   // bytes per buffer = 13824

__global__ __launch_bounds__(NTHR, 3)
void corr_kernel(const float* __restrict__ A, const float* __restrict__ Bm,
                 float* __restrict__ O) {
    __shared__ __align__(16) float sB[2][CC][BR][BW];   // 27.6 KB

    const int t  = threadIdx.x;
    const int xq = t & 31;
    const int yy = t >> 5;
    const int x0 = xq << 2;

    const int y0 = blockIdx.x * TY;
    const int p0 = (int)blockIdx.y * 3 - 4;
    const int bb = blockIdx.z;

    const float* Ab = A  + (size_t)bb * 2097152;
    const float* Bb = Bm + (size_t)bb * 2097152;

    // ---- zero both buffers once (halo + invalid rows stay zero forever) ----
    float4* sB4 = (float4*)&sB[0][0][0][0];
#pragma unroll
    for (int i = 0; i < (2 * CC * BR * BW / 4) / NTHR + 1; i++) {
        int idx = t + i * NTHR;
        if (idx < 2 * CC * BR * BW / 4) sB4[idx] = make_float4(0.f, 0.f, 0.f, 0.f);
    }

    // ---- hoisted per-thread fill descriptors: 6 float4 interior slots ----
    const float* gptr[6];
    unsigned     sb0[6];
    bool         valid[6];
#pragma unroll
    for (int k = 0; k < 6; k++) {
        int idx = k * NTHR + t;        // 0..767
        int col = idx & 31;            // float4 col within 128-wide interior
        int row = idx >> 5;            // 0..23
        int c   = row / 6;
        int r   = row - c * 6;
        int gy  = y0 + p0 + r;
        valid[k] = (unsigned)gy < 128u;
        gptr[k]  = Bb + (size_t)c * 16384 + gy * 128 + col * 4;
        sb0[k]   = (unsigned)__cvta_generic_to_shared(&sB[0][c][r][4 + col * 4]);
    }
    __syncthreads();   // zeros visible before any cp.async lands

    // ---- prologue: fill buffer 0 with chunk 0 ----
#pragma unroll
    for (int k = 0; k < 6; k++) {
        if (valid[k])
            asm volatile("cp.async.cg.shared.global [%0], [%1], 16;\n"
                         :: "r"(sb0[k]), "l"(gptr[k]));
        gptr[k] += CC * 16384;
    }
    asm volatile("cp.async.commit_group;\n" ::: "memory");

    float acc[3][9][4];
#pragma unroll
    for (int pp = 0; pp < 3; pp++)
#pragma unroll
        for (int q = 0; q < 9; q++)
#pragma unroll
            for (int j = 0; j < 4; j++) acc[pp][q][j] = 0.0f;

    const float* Arow = Ab + (y0 + yy) * 128 + x0;

    for (int chunk = 0; chunk < NCH; chunk++) {
        const int cc   = chunk * CC;
        const int buf  = chunk & 1;
        const int nbuf = buf ^ 1;

        // prefetch A (independent of smem; overlaps wait+barrier)
        float4 av[CC];
#pragma unroll
        for (int c = 0; c < CC; c++)
            av[c] = *(const float4*)(Arow + (size_t)(cc + c) * 16384);

        asm volatile("cp.async.wait_group 0;\n" ::: "memory");
        __syncthreads();   // buf ready for all; all done computing on nbuf

        // issue fill for next chunk into nbuf (overlaps compute below)
        if (chunk + 1 < NCH) {
#pragma unroll
            for (int k = 0; k < 6; k++) {
                if (valid[k])
                    asm volatile("cp.async.cg.shared.global [%0], [%1], 16;\n"
                                 :: "r"(sb0[k] + nbuf * SBHALF), "l"(gptr[k]));
                gptr[k] += CC * 16384;
            }
        }
        asm volatile("cp.async.commit_group;\n" ::: "memory");

        // ---- compute: 4 ch x 3 p x 9 q x 4 x = 432 FFMA ----
#pragma unroll
        for (int c = 0; c < CC; c++) {
#pragma unroll
            for (int pp = 0; pp < 3; pp++) {
                const float* row = &sB[buf][c][yy + pp][0];
                float w[12];
                *(float4*)&w[0] = *(const float4*)&row[x0];
                *(float4*)&w[4] = *(const float4*)&row[x0 + 4];
                *(float4*)&w[8] = *(const float4*)&row[x0 + 8];
#pragma unroll
                for (int q = 0; q < 9; q++) {
                    acc[pp][q][0] += av[c].x * w[q];
                    acc[pp][q][1] += av[c].y * w[q + 1];
                    acc[pp][q][2] += av[c].z * w[q + 2];
                    acc[pp][q][3] += av[c].w * w[q + 3];
                }
            }
        }
    }

    // ---- epilogue: scale, float4 coalesced stores ----
    const float scale = 1.0f / 128.0f;
    float* Ob = O + (size_t)bb * 81 * 16384;
#pragma unroll
    for (int pp = 0; pp < 3; pp++) {
        int dbase = (p0 + pp + 4) * 9;
#pragma unroll
        for (int q = 0; q < 9; q++) {
            float4 v;
            v.x = acc[pp][q][0] * scale;
            v.y = acc[pp][q][1] * scale;
            v.z = acc[pp][q][2] * scale;
            v.w = acc[pp][q][3] * scale;
            *(float4*)&Ob[(size_t)(dbase + q) * 16384 + (y0 + yy) * 128 + x0] = v;
        }
    }
}

extern "C" void kernel_launch(void* const* d_in, const int* in_sizes, int n_in,
                              void* d_out, int out_size) {
    const float* A = (const float*)d_in[0];
    const float* B = (const float*)d_in[1];
    float*       O = (float*)d_out;

    dim3 grid(32, 3, 8);
    corr_kernel<<<grid, NTHR>>>(A, B, O);
}